// round 16
// baseline (speedup 1.0000x reference)
#include <cuda_runtime.h>
#include <cuda_fp16.h>
#include <math_constants.h>

#define NN 10000
#define NE 320000

// ---------------- scratch (static device globals; no runtime allocation) ----------------
__device__ __half g_feat1h[NN * 256]; // layer-1 projected features [N, H*D] (fp16)
__device__ float g_h[NN * 256];       // layer-1 output after edge-softmax agg + elu
__device__ float g_el1[NN * 4];
__device__ float g_er1[NN * 4];
__device__ float g_feat2[NN * 48];    // padded rows (col 47 zero)
__device__ float g_el2[NN];
__device__ float g_er2[NN];
__device__ int   g_deg[NN];
__device__ int   g_rank[NE];
__device__ int   g_rowstart[NN + 1];
__device__ int   g_csr_src[NE];

__device__ __forceinline__ float lrelu(float x) { return x > 0.f ? x : 0.2f * x; }

// ---------------- CSR build ----------------
__global__ void init_kernel() {
    int i = blockIdx.x * blockDim.x + threadIdx.x;
    if (i < NN) g_deg[i] = 0;
}

__global__ void count_kernel(const int* __restrict__ dst) {
    int e = blockIdx.x * blockDim.x + threadIdx.x;
    if (e < NE) g_rank[e] = atomicAdd(&g_deg[dst[e]], 1);
}

__global__ void scan_kernel() {
    __shared__ int sh[1024];
    int t = threadIdx.x;
    const int CH = 10;                 // 1024*10 >= NN
    int base = t * CH;
    int local[CH];
    int s = 0;
#pragma unroll
    for (int i = 0; i < CH; i++) {
        int idx = base + i;
        int d = (idx < NN) ? g_deg[idx] : 0;
        local[i] = d; s += d;
    }
    sh[t] = s;
    __syncthreads();
    for (int off = 1; off < 1024; off <<= 1) {
        int v = (t >= off) ? sh[t - off] : 0;
        __syncthreads();
        sh[t] += v;
        __syncthreads();
    }
    int offset = sh[t] - s;            // exclusive prefix
#pragma unroll
    for (int i = 0; i < CH; i++) {
        int idx = base + i;
        if (idx < NN) g_rowstart[idx] = offset;
        offset += local[i];
    }
    if (t == 1023) g_rowstart[NN] = offset;   // == NE
}

__global__ void scatter_kernel(const int* __restrict__ src, const int* __restrict__ dst) {
    int e = blockIdx.x * blockDim.x + threadIdx.x;
    if (e < NE)
        g_csr_src[g_rowstart[dst[e]] + g_rank[e]] = src[e];
}

// ---------------- GEMM1: feat1 = features @ W1  ([NN,256] x [256,256]) ----------------
__global__ __launch_bounds__(256) void gemm1_kernel(const float* __restrict__ A,
                                                    const float* __restrict__ B,
                                                    const float* __restrict__ al1,
                                                    const float* __restrict__ ar1) {
    __shared__ float As[16][128];
    __shared__ float Bs[16][128];
    int tid = threadIdx.x;             // 256 threads
    int tx = tid & 15, ty = tid >> 4;
    int rowBase = blockIdx.y * 128, colBase = blockIdx.x * 128;

    int hLocal = tx >> 3;                       // 0..1
    int head = blockIdx.x * 2 + hLocal;         // global head index
    int cseg = (tx & 7) * 8;                    // col offset within head
    float alv[8], arv[8];
#pragma unroll
    for (int j = 0; j < 8; j++) {
        alv[j] = al1[head * 64 + cseg + j];
        arv[j] = ar1[head * 64 + cseg + j];
    }

    int aI0 = tid,        aI1 = tid + 256;
    int aR0 = aI0 >> 2,   aK0 = (aI0 & 3) * 4;
    int aR1 = aI1 >> 2,   aK1 = (aI1 & 3) * 4;
    int bK0 = aI0 >> 5,   bN0 = (aI0 & 31) * 4;
    int bK1 = aI1 >> 5,   bN1 = (aI1 & 31) * 4;

    float4 pa0, pa1, pb0, pb1;
    {
        int r0 = rowBase + aR0, r1 = rowBase + aR1;
        pa0 = (r0 < NN) ? *(const float4*)&A[r0 * 256 + aK0] : make_float4(0.f, 0.f, 0.f, 0.f);
        pa1 = (r1 < NN) ? *(const float4*)&A[r1 * 256 + aK1] : make_float4(0.f, 0.f, 0.f, 0.f);
        pb0 = *(const float4*)&B[bK0 * 256 + colBase + bN0];
        pb1 = *(const float4*)&B[bK1 * 256 + colBase + bN1];
    }

    unsigned long long acc[8][4];
#pragma unroll
    for (int i = 0; i < 8; i++)
#pragma unroll
        for (int j = 0; j < 4; j++) acc[i][j] = 0ull;

    for (int t = 0; t < 16; t++) {
        As[aK0 + 0][aR0] = pa0.x; As[aK0 + 1][aR0] = pa0.y;
        As[aK0 + 2][aR0] = pa0.z; As[aK0 + 3][aR0] = pa0.w;
        As[aK1 + 0][aR1] = pa1.x; As[aK1 + 1][aR1] = pa1.y;
        As[aK1 + 2][aR1] = pa1.z; As[aK1 + 3][aR1] = pa1.w;
        *(float4*)&Bs[bK0][bN0] = pb0;
        *(float4*)&Bs[bK1][bN1] = pb1;
        __syncthreads();
        if (t < 15) {
            int k0 = (t + 1) * 16;
            int r0 = rowBase + aR0, r1 = rowBase + aR1;
            pa0 = (r0 < NN) ? *(const float4*)&A[r0 * 256 + k0 + aK0] : make_float4(0.f, 0.f, 0.f, 0.f);
            pa1 = (r1 < NN) ? *(const float4*)&A[r1 * 256 + k0 + aK1] : make_float4(0.f, 0.f, 0.f, 0.f);
            pb0 = *(const float4*)&B[(k0 + bK0) * 256 + colBase + bN0];
            pb1 = *(const float4*)&B[(k0 + bK1) * 256 + colBase + bN1];
        }
#pragma unroll
        for (int k = 0; k < 16; k++) {
            float4 a0 = *(const float4*)&As[k][ty * 8];
            float4 a1 = *(const float4*)&As[k][ty * 8 + 4];
            ulonglong2 bq0 = *(const ulonglong2*)&Bs[k][tx * 8];
            ulonglong2 bq1 = *(const ulonglong2*)&Bs[k][tx * 8 + 4];
            unsigned long long bp0 = bq0.x, bp1 = bq0.y, bp2 = bq1.x, bp3 = bq1.y;
            float av[8] = {a0.x, a0.y, a0.z, a0.w, a1.x, a1.y, a1.z, a1.w};
#pragma unroll
            for (int i = 0; i < 8; i++) {
                unsigned long long ad;
                asm("mov.b64 %0, {%1, %1};" : "=l"(ad) : "f"(av[i]));
                asm("fma.rn.f32x2 %0, %1, %2, %0;" : "+l"(acc[i][0]) : "l"(ad), "l"(bp0));
                asm("fma.rn.f32x2 %0, %1, %2, %0;" : "+l"(acc[i][1]) : "l"(ad), "l"(bp1));
                asm("fma.rn.f32x2 %0, %1, %2, %0;" : "+l"(acc[i][2]) : "l"(ad), "l"(bp2));
                asm("fma.rn.f32x2 %0, %1, %2, %0;" : "+l"(acc[i][3]) : "l"(ad), "l"(bp3));
            }
        }
        __syncthreads();
    }

#pragma unroll
    for (int i = 0; i < 8; i++) {
        int row = rowBase + ty * 8 + i;
        float c[8];
#pragma unroll
        for (int j = 0; j < 4; j++)
            asm("mov.b64 {%0, %1}, %2;" : "=f"(c[2 * j]), "=f"(c[2 * j + 1]) : "l"(acc[i][j]));
        float el = 0.f, er = 0.f;
#pragma unroll
        for (int j = 0; j < 8; j++) {
            el = fmaf(c[j], alv[j], el);
            er = fmaf(c[j], arv[j], er);
        }
#pragma unroll
        for (int off = 4; off; off >>= 1) {
            el += __shfl_xor_sync(0xffffffffu, el, off);
            er += __shfl_xor_sync(0xffffffffu, er, off);
        }
        if (row < NN) {
            __half2 hp[4];
#pragma unroll
            for (int j = 0; j < 4; j++)
                hp[j] = __floats2half2_rn(c[2 * j], c[2 * j + 1]);
            *(uint4*)&g_feat1h[row * 256 + colBase + tx * 8] = *(uint4*)hp;
            if ((tx & 7) == 0) {
                g_el1[row * 4 + head] = el;
                g_er1[row * 4 + head] = er;
            }
        }
    }
}

// ---------------- layer-1 edge softmax + aggregation + ELU ----------------
// Single pass (no max subtraction: logits analytically bounded, softmax invariant),
// 2 warps per node, MLP=4 unrolled edge loop. Per-lane dn is replicated -> no shuffles.
__global__ void gather1_kernel() {
    int gw = (blockIdx.x * blockDim.x + threadIdx.x) >> 5;
    int lane = threadIdx.x & 31;
    if (gw >= NN * 2) return;
    int node = gw >> 1, pair = gw & 1;
    int beg = g_rowstart[node], end = g_rowstart[node + 1];
    int hsub = lane >> 4;
    int hsel = pair * 2 + hsub;
    float erh = g_er1[node * 4 + hsel];
    int coff = pair * 128 + lane * 4;

    float4 acc = make_float4(0.f, 0.f, 0.f, 0.f);
    float dn = 0.f;
    int i = beg;
    for (; i + 4 <= end; i += 4) {
        int s0 = g_csr_src[i],     s1 = g_csr_src[i + 1];
        int s2 = g_csr_src[i + 2], s3 = g_csr_src[i + 3];
        float e0 = g_el1[s0 * 4 + hsel], e1 = g_el1[s1 * 4 + hsel];
        float e2 = g_el1[s2 * 4 + hsel], e3 = g_el1[s3 * 4 + hsel];
        uint2 u0 = *(const uint2*)&g_feat1h[s0 * 256 + coff];
        uint2 u1 = *(const uint2*)&g_feat1h[s1 * 256 + coff];
        uint2 u2 = *(const uint2*)&g_feat1h[s2 * 256 + coff];
        uint2 u3 = *(const uint2*)&g_feat1h[s3 * 256 + coff];
        float a0 = __expf(lrelu(e0 + erh));
        float a1 = __expf(lrelu(e1 + erh));
        float a2 = __expf(lrelu(e2 + erh));
        float a3 = __expf(lrelu(e3 + erh));
        dn += (a0 + a1) + (a2 + a3);
        float2 f;
        f = __half22float2(*(__half2*)&u0.x); acc.x = fmaf(a0, f.x, acc.x); acc.y = fmaf(a0, f.y, acc.y);
        f = __half22float2(*(__half2*)&u0.y); acc.z = fmaf(a0, f.x, acc.z); acc.w = fmaf(a0, f.y, acc.w);
        f = __half22float2(*(__half2*)&u1.x); acc.x = fmaf(a1, f.x, acc.x); acc.y = fmaf(a1, f.y, acc.y);
        f = __half22float2(*(__half2*)&u1.y); acc.z = fmaf(a1, f.x, acc.z); acc.w = fmaf(a1, f.y, acc.w);
        f = __half22float2(*(__half2*)&u2.x); acc.x = fmaf(a2, f.x, acc.x); acc.y = fmaf(a2, f.y, acc.y);
        f = __half22float2(*(__half2*)&u2.y); acc.z = fmaf(a2, f.x, acc.z); acc.w = fmaf(a2, f.y, acc.w);
        f = __half22float2(*(__half2*)&u3.x); acc.x = fmaf(a3, f.x, acc.x); acc.y = fmaf(a3, f.y, acc.y);
        f = __half22float2(*(__half2*)&u3.y); acc.z = fmaf(a3, f.x, acc.z); acc.w = fmaf(a3, f.y, acc.w);
    }
    for (; i < end; i++) {
        int s = g_csr_src[i];
        float a = __expf(lrelu(g_el1[s * 4 + hsel] + erh));
        uint2 u = *(const uint2*)&g_feat1h[s * 256 + coff];
        float2 f0 = __half22float2(*(__half2*)&u.x);
        float2 f1 = __half22float2(*(__half2*)&u.y);
        dn += a;
        acc.x = fmaf(a, f0.x, acc.x); acc.y = fmaf(a, f0.y, acc.y);
        acc.z = fmaf(a, f1.x, acc.z); acc.w = fmaf(a, f1.y, acc.w);
    }
    float inv = 1.f / fmaxf(dn, 1e-9f);
    acc.x *= inv; acc.y *= inv; acc.z *= inv; acc.w *= inv;
    acc.x = acc.x > 0.f ? acc.x : __expf(acc.x) - 1.f;
    acc.y = acc.y > 0.f ? acc.y : __expf(acc.y) - 1.f;
    acc.z = acc.z > 0.f ? acc.z : __expf(acc.z) - 1.f;
    acc.w = acc.w > 0.f ? acc.w : __expf(acc.w) - 1.f;
    *(float4*)&g_h[node * 256 + coff] = acc;
}

// ---------------- GEMM2: feat2 = h @ W2  ([NN,256] x [256,47->64pad]), fused el2/er2 ----
// 64x64 tile, 4x4 microtile, f32x2 FMA, W2 staged per k-chunk (cols 47..63 zero).
__global__ __launch_bounds__(256) void gemm2_kernel(const float* __restrict__ W2,
                                                    const float* __restrict__ al2,
                                                    const float* __restrict__ ar2) {
    __shared__ float As[16][64];
    __shared__ float Bs[16][64];
    int tid = threadIdx.x;             // 256 threads
    int tx = tid & 15, ty = tid >> 4;
    int rowBase = blockIdx.x * 64;
    int c0 = tx * 4;

    float alv[4], arv[4];
#pragma unroll
    for (int j = 0; j < 4; j++) {
        int c = c0 + j;
        alv[j] = (c < 47) ? al2[c] : 0.f;
        arv[j] = (c < 47) ? ar2[c] : 0.f;
    }

    int aR = tid >> 2, aK = (tid & 3) * 4;      // A: 64 rows x 16 k
    int bK = tid >> 4, bC = (tid & 15) * 4;     // B: 16 k x 64 cols

    unsigned long long acc[4][2];
#pragma unroll
    for (int i = 0; i < 4; i++) { acc[i][0] = 0ull; acc[i][1] = 0ull; }

    for (int k0 = 0; k0 < 256; k0 += 16) {
        int row = rowBase + aR;
        float4 va = (row < NN) ? *(const float4*)&g_h[row * 256 + k0 + aK]
                               : make_float4(0.f, 0.f, 0.f, 0.f);
        As[aK + 0][aR] = va.x; As[aK + 1][aR] = va.y;
        As[aK + 2][aR] = va.z; As[aK + 3][aR] = va.w;
#pragma unroll
        for (int j = 0; j < 4; j++) {
            int c = bC + j;
            Bs[bK][c] = (c < 47) ? W2[(k0 + bK) * 47 + c] : 0.f;
        }
        __syncthreads();
#pragma unroll
        for (int k = 0; k < 16; k++) {
            float4 a4 = *(const float4*)&As[k][ty * 4];
            ulonglong2 bq = *(const ulonglong2*)&Bs[k][tx * 4];
            float av[4] = {a4.x, a4.y, a4.z, a4.w};
#pragma unroll
            for (int i = 0; i < 4; i++) {
                unsigned long long ad;
                asm("mov.b64 %0, {%1, %1};" : "=l"(ad) : "f"(av[i]));
                asm("fma.rn.f32x2 %0, %1, %2, %0;" : "+l"(acc[i][0]) : "l"(ad), "l"(bq.x));
                asm("fma.rn.f32x2 %0, %1, %2, %0;" : "+l"(acc[i][1]) : "l"(ad), "l"(bq.y));
            }
        }
        __syncthreads();
    }

#pragma unroll
    for (int i = 0; i < 4; i++) {
        int row = rowBase + ty * 4 + i;
        float c[4];
        asm("mov.b64 {%0, %1}, %2;" : "=f"(c[0]), "=f"(c[1]) : "l"(acc[i][0]));
        asm("mov.b64 {%0, %1}, %2;" : "=f"(c[2]), "=f"(c[3]) : "l"(acc[i][1]));
        float el = 0.f, er = 0.f;
#pragma unroll
        for (int j = 0; j < 4; j++) {
            el = fmaf(c[j], alv[j], el);
            er = fmaf(c[j], arv[j], er);
        }
        // reduce across 16 col-threads (contiguous 16-lane halves of the warp)
#pragma unroll
        for (int off = 8; off; off >>= 1) {
            el += __shfl_xor_sync(0xffffffffu, el, off);
            er += __shfl_xor_sync(0xffffffffu, er, off);
        }
        if (row < NN) {
            if (tx < 12) {
                float4 st = make_float4(c[0], c[1], c[2], (c0 + 3 < 47) ? c[3] : 0.f);
                *(float4*)&g_feat2[row * 48 + c0] = st;
            }
            if (tx == 0) { g_el2[row] = el; g_er2[row] = er; }
        }
    }
}

// ---------------- layer-2 gather + fused log-softmax (warp per node, single pass) ------
__global__ void gather2_kernel(float* __restrict__ out) {
    int gw = (blockIdx.x * blockDim.x + threadIdx.x) >> 5;
    int lane = threadIdx.x & 31;
    if (gw >= NN) return;
    int node = gw;
    int beg = g_rowstart[node], end = g_rowstart[node + 1];
    float erv = g_er2[node];
    int j1 = lane + 32;
    bool hasJ1 = (j1 < 47);
    int j1c = hasJ1 ? j1 : 47;                 // col 47 is zero-padded

    float acc0 = 0.f, acc1 = 0.f, dn = 0.f;
    int i = beg;
    for (; i + 4 <= end; i += 4) {
        int s0 = g_csr_src[i],     s1 = g_csr_src[i + 1];
        int s2 = g_csr_src[i + 2], s3 = g_csr_src[i + 3];
        float e0 = g_el2[s0], e1 = g_el2[s1], e2 = g_el2[s2], e3 = g_el2[s3];
        float f00 = g_feat2[s0 * 48 + lane], f01 = g_feat2[s0 * 48 + j1c];
        float f10 = g_feat2[s1 * 48 + lane], f11 = g_feat2[s1 * 48 + j1c];
        float f20 = g_feat2[s2 * 48 + lane], f21 = g_feat2[s2 * 48 + j1c];
        float f30 = g_feat2[s3 * 48 + lane], f31 = g_feat2[s3 * 48 + j1c];
        float a0 = __expf(lrelu(e0 + erv));
        float a1 = __expf(lrelu(e1 + erv));
        float a2 = __expf(lrelu(e2 + erv));
        float a3 = __expf(lrelu(e3 + erv));
        dn += (a0 + a1) + (a2 + a3);
        acc0 = fmaf(a0, f00, acc0); acc1 = fmaf(a0, f01, acc1);
        acc0 = fmaf(a1, f10, acc0); acc1 = fmaf(a1, f11, acc1);
        acc0 = fmaf(a2, f20, acc0); acc1 = fmaf(a2, f21, acc1);
        acc0 = fmaf(a3, f30, acc0); acc1 = fmaf(a3, f31, acc1);
    }
    for (; i < end; i++) {
        int s = g_csr_src[i];
        float a = __expf(lrelu(g_el2[s] + erv));
        dn += a;
        acc0 = fmaf(a, g_feat2[s * 48 + lane], acc0);
        acc1 = fmaf(a, g_feat2[s * 48 + j1c], acc1);
    }
    float inv = 1.f / fmaxf(dn, 1e-9f);
    acc0 *= inv; acc1 *= inv;

    // log_softmax over 47 logits
    float m2 = fmaxf(acc0, hasJ1 ? acc1 : -CUDART_INF_F);
#pragma unroll
    for (int off = 16; off; off >>= 1)
        m2 = fmaxf(m2, __shfl_xor_sync(0xffffffffu, m2, off));
    float se = __expf(acc0 - m2) + (hasJ1 ? __expf(acc1 - m2) : 0.f);
#pragma unroll
    for (int off = 16; off; off >>= 1)
        se += __shfl_xor_sync(0xffffffffu, se, off);
    float ls = logf(se);
    out[node * 47 + lane] = acc0 - m2 - ls;
    if (hasJ1) out[node * 47 + j1] = acc1 - m2 - ls;
}

// ---------------- launch ----------------
extern "C" void kernel_launch(void* const* d_in, const int* in_sizes, int n_in,
                              void* d_out, int out_size) {
    const float* features = (const float*)d_in[0];
    const int*   src      = (const int*)  d_in[1];
    const int*   dst      = (const int*)  d_in[2];
    const float* W1       = (const float*)d_in[3];
    const float* al1      = (const float*)d_in[4];
    const float* ar1      = (const float*)d_in[5];
    const float* W2       = (const float*)d_in[6];
    const float* al2      = (const float*)d_in[7];
    const float* ar2      = (const float*)d_in[8];
    float* out = (float*)d_out;

    // Fork the CSR build onto a side stream so it overlaps GEMM1.
    cudaStream_t s2;
    cudaEvent_t evFork, evJoin;
    cudaStreamCreateWithFlags(&s2, cudaStreamNonBlocking);
    cudaEventCreateWithFlags(&evFork, cudaEventDisableTiming);
    cudaEventCreateWithFlags(&evJoin, cudaEventDisableTiming);

    cudaEventRecord(evFork, 0);
    cudaStreamWaitEvent(s2, evFork, 0);
    init_kernel<<<(NN + 255) / 256, 256, 0, s2>>>();
    count_kernel<<<(NE + 255) / 256, 256, 0, s2>>>(dst);
    scan_kernel<<<1, 1024, 0, s2>>>();
    scatter_kernel<<<(NE + 255) / 256, 256, 0, s2>>>(src, dst);
    cudaEventRecord(evJoin, s2);

    dim3 g1(2, (NN + 127) / 128);
    gemm1_kernel<<<g1, 256>>>(features, W1, al1, ar1);

    cudaStreamWaitEvent(0, evJoin, 0);
    gather1_kernel<<<(2 * NN + 7) / 8, 256>>>();
    gemm2_kernel<<<(NN + 63) / 64, 256>>>(W2, al2, ar2);
    gather2_kernel<<<(NN + 7) / 8, 256>>>(out);
}

// round 17
// speedup vs baseline: 1.0086x; 1.0086x over previous
#include <cuda_runtime.h>
#include <cuda_fp16.h>
#include <math_constants.h>

#define NN 10000
#define NE 320000

// ---------------- scratch (static device globals; no runtime allocation) ----------------
__device__ __half g_feat1h[NN * 256]; // layer-1 projected features [N, H*D] (fp16)
__device__ float g_h[NN * 256];       // layer-1 output after edge-softmax agg + elu
__device__ float g_el1[NN * 4];
__device__ float g_er1[NN * 4];
__device__ float g_feat2[NN * 48];    // padded rows (col 47 zero)
__device__ float g_el2[NN];
__device__ float g_er2[NN];
__device__ int   g_deg[NN];
__device__ int   g_rank[NE];
__device__ int   g_rowstart[NN + 1];
__device__ int   g_csr_src[NE];

__device__ __forceinline__ float lrelu(float x) { return x > 0.f ? x : 0.2f * x; }

// ---------------- CSR build ----------------
__global__ void init_kernel() {
    int i = blockIdx.x * blockDim.x + threadIdx.x;
    if (i < NN) g_deg[i] = 0;
}

__global__ void count_kernel(const int* __restrict__ dst) {
    int e = blockIdx.x * blockDim.x + threadIdx.x;
    if (e < NE) g_rank[e] = atomicAdd(&g_deg[dst[e]], 1);
}

__global__ void scan_kernel() {
    __shared__ int sh[1024];
    int t = threadIdx.x;
    const int CH = 10;                 // 1024*10 >= NN
    int base = t * CH;
    int local[CH];
    int s = 0;
#pragma unroll
    for (int i = 0; i < CH; i++) {
        int idx = base + i;
        int d = (idx < NN) ? g_deg[idx] : 0;
        local[i] = d; s += d;
    }
    sh[t] = s;
    __syncthreads();
    for (int off = 1; off < 1024; off <<= 1) {
        int v = (t >= off) ? sh[t - off] : 0;
        __syncthreads();
        sh[t] += v;
        __syncthreads();
    }
    int offset = sh[t] - s;            // exclusive prefix
#pragma unroll
    for (int i = 0; i < CH; i++) {
        int idx = base + i;
        if (idx < NN) g_rowstart[idx] = offset;
        offset += local[i];
    }
    if (t == 1023) g_rowstart[NN] = offset;   // == NE
}

__global__ void scatter_kernel(const int* __restrict__ src, const int* __restrict__ dst) {
    int e = blockIdx.x * blockDim.x + threadIdx.x;
    if (e < NE)
        g_csr_src[g_rowstart[dst[e]] + g_rank[e]] = src[e];
}

// ---------------- GEMM1: feat1 = features @ W1  ([NN,256] x [256,256]) ----------------
__global__ __launch_bounds__(256) void gemm1_kernel(const float* __restrict__ A,
                                                    const float* __restrict__ B,
                                                    const float* __restrict__ al1,
                                                    const float* __restrict__ ar1) {
    __shared__ float As[16][128];
    __shared__ float Bs[16][128];
    int tid = threadIdx.x;             // 256 threads
    int tx = tid & 15, ty = tid >> 4;
    int rowBase = blockIdx.y * 128, colBase = blockIdx.x * 128;

    int hLocal = tx >> 3;                       // 0..1
    int head = blockIdx.x * 2 + hLocal;         // global head index
    int cseg = (tx & 7) * 8;                    // col offset within head
    float alv[8], arv[8];
#pragma unroll
    for (int j = 0; j < 8; j++) {
        alv[j] = al1[head * 64 + cseg + j];
        arv[j] = ar1[head * 64 + cseg + j];
    }

    int aI0 = tid,        aI1 = tid + 256;
    int aR0 = aI0 >> 2,   aK0 = (aI0 & 3) * 4;
    int aR1 = aI1 >> 2,   aK1 = (aI1 & 3) * 4;
    int bK0 = aI0 >> 5,   bN0 = (aI0 & 31) * 4;
    int bK1 = aI1 >> 5,   bN1 = (aI1 & 31) * 4;

    float4 pa0, pa1, pb0, pb1;
    {
        int r0 = rowBase + aR0, r1 = rowBase + aR1;
        pa0 = (r0 < NN) ? *(const float4*)&A[r0 * 256 + aK0] : make_float4(0.f, 0.f, 0.f, 0.f);
        pa1 = (r1 < NN) ? *(const float4*)&A[r1 * 256 + aK1] : make_float4(0.f, 0.f, 0.f, 0.f);
        pb0 = *(const float4*)&B[bK0 * 256 + colBase + bN0];
        pb1 = *(const float4*)&B[bK1 * 256 + colBase + bN1];
    }

    unsigned long long acc[8][4];
#pragma unroll
    for (int i = 0; i < 8; i++)
#pragma unroll
        for (int j = 0; j < 4; j++) acc[i][j] = 0ull;

    for (int t = 0; t < 16; t++) {
        As[aK0 + 0][aR0] = pa0.x; As[aK0 + 1][aR0] = pa0.y;
        As[aK0 + 2][aR0] = pa0.z; As[aK0 + 3][aR0] = pa0.w;
        As[aK1 + 0][aR1] = pa1.x; As[aK1 + 1][aR1] = pa1.y;
        As[aK1 + 2][aR1] = pa1.z; As[aK1 + 3][aR1] = pa1.w;
        *(float4*)&Bs[bK0][bN0] = pb0;
        *(float4*)&Bs[bK1][bN1] = pb1;
        __syncthreads();
        if (t < 15) {
            int k0 = (t + 1) * 16;
            int r0 = rowBase + aR0, r1 = rowBase + aR1;
            pa0 = (r0 < NN) ? *(const float4*)&A[r0 * 256 + k0 + aK0] : make_float4(0.f, 0.f, 0.f, 0.f);
            pa1 = (r1 < NN) ? *(const float4*)&A[r1 * 256 + k0 + aK1] : make_float4(0.f, 0.f, 0.f, 0.f);
            pb0 = *(const float4*)&B[(k0 + bK0) * 256 + colBase + bN0];
            pb1 = *(const float4*)&B[(k0 + bK1) * 256 + colBase + bN1];
        }
#pragma unroll
        for (int k = 0; k < 16; k++) {
            float4 a0 = *(const float4*)&As[k][ty * 8];
            float4 a1 = *(const float4*)&As[k][ty * 8 + 4];
            ulonglong2 bq0 = *(const ulonglong2*)&Bs[k][tx * 8];
            ulonglong2 bq1 = *(const ulonglong2*)&Bs[k][tx * 8 + 4];
            unsigned long long bp0 = bq0.x, bp1 = bq0.y, bp2 = bq1.x, bp3 = bq1.y;
            float av[8] = {a0.x, a0.y, a0.z, a0.w, a1.x, a1.y, a1.z, a1.w};
#pragma unroll
            for (int i = 0; i < 8; i++) {
                unsigned long long ad;
                asm("mov.b64 %0, {%1, %1};" : "=l"(ad) : "f"(av[i]));
                asm("fma.rn.f32x2 %0, %1, %2, %0;" : "+l"(acc[i][0]) : "l"(ad), "l"(bp0));
                asm("fma.rn.f32x2 %0, %1, %2, %0;" : "+l"(acc[i][1]) : "l"(ad), "l"(bp1));
                asm("fma.rn.f32x2 %0, %1, %2, %0;" : "+l"(acc[i][2]) : "l"(ad), "l"(bp2));
                asm("fma.rn.f32x2 %0, %1, %2, %0;" : "+l"(acc[i][3]) : "l"(ad), "l"(bp3));
            }
        }
        __syncthreads();
    }

#pragma unroll
    for (int i = 0; i < 8; i++) {
        int row = rowBase + ty * 8 + i;
        float c[8];
#pragma unroll
        for (int j = 0; j < 4; j++)
            asm("mov.b64 {%0, %1}, %2;" : "=f"(c[2 * j]), "=f"(c[2 * j + 1]) : "l"(acc[i][j]));
        float el = 0.f, er = 0.f;
#pragma unroll
        for (int j = 0; j < 8; j++) {
            el = fmaf(c[j], alv[j], el);
            er = fmaf(c[j], arv[j], er);
        }
#pragma unroll
        for (int off = 4; off; off >>= 1) {
            el += __shfl_xor_sync(0xffffffffu, el, off);
            er += __shfl_xor_sync(0xffffffffu, er, off);
        }
        if (row < NN) {
            __half2 hp[4];
#pragma unroll
            for (int j = 0; j < 4; j++)
                hp[j] = __floats2half2_rn(c[2 * j], c[2 * j + 1]);
            *(uint4*)&g_feat1h[row * 256 + colBase + tx * 8] = *(uint4*)hp;
            if ((tx & 7) == 0) {
                g_el1[row * 4 + head] = el;
                g_er1[row * 4 + head] = er;
            }
        }
    }
}

// ---------------- layer-1 edge softmax + aggregation + ELU ----------------
// Single pass (no max subtraction: logits analytically bounded, softmax invariant),
// 2 warps per node, MLP=4 unrolled edge loop. Per-lane dn is replicated -> no shuffles.
__global__ void gather1_kernel() {
    int gw = (blockIdx.x * blockDim.x + threadIdx.x) >> 5;
    int lane = threadIdx.x & 31;
    if (gw >= NN * 2) return;
    int node = gw >> 1, pair = gw & 1;
    int beg = g_rowstart[node], end = g_rowstart[node + 1];
    int hsub = lane >> 4;
    int hsel = pair * 2 + hsub;
    float erh = g_er1[node * 4 + hsel];
    int coff = pair * 128 + lane * 4;

    float4 acc = make_float4(0.f, 0.f, 0.f, 0.f);
    float dn = 0.f;
    int i = beg;
    for (; i + 4 <= end; i += 4) {
        int s0 = g_csr_src[i],     s1 = g_csr_src[i + 1];
        int s2 = g_csr_src[i + 2], s3 = g_csr_src[i + 3];
        float e0 = g_el1[s0 * 4 + hsel], e1 = g_el1[s1 * 4 + hsel];
        float e2 = g_el1[s2 * 4 + hsel], e3 = g_el1[s3 * 4 + hsel];
        uint2 u0 = *(const uint2*)&g_feat1h[s0 * 256 + coff];
        uint2 u1 = *(const uint2*)&g_feat1h[s1 * 256 + coff];
        uint2 u2 = *(const uint2*)&g_feat1h[s2 * 256 + coff];
        uint2 u3 = *(const uint2*)&g_feat1h[s3 * 256 + coff];
        float a0 = __expf(lrelu(e0 + erh));
        float a1 = __expf(lrelu(e1 + erh));
        float a2 = __expf(lrelu(e2 + erh));
        float a3 = __expf(lrelu(e3 + erh));
        dn += (a0 + a1) + (a2 + a3);
        float2 f;
        f = __half22float2(*(__half2*)&u0.x); acc.x = fmaf(a0, f.x, acc.x); acc.y = fmaf(a0, f.y, acc.y);
        f = __half22float2(*(__half2*)&u0.y); acc.z = fmaf(a0, f.x, acc.z); acc.w = fmaf(a0, f.y, acc.w);
        f = __half22float2(*(__half2*)&u1.x); acc.x = fmaf(a1, f.x, acc.x); acc.y = fmaf(a1, f.y, acc.y);
        f = __half22float2(*(__half2*)&u1.y); acc.z = fmaf(a1, f.x, acc.z); acc.w = fmaf(a1, f.y, acc.w);
        f = __half22float2(*(__half2*)&u2.x); acc.x = fmaf(a2, f.x, acc.x); acc.y = fmaf(a2, f.y, acc.y);
        f = __half22float2(*(__half2*)&u2.y); acc.z = fmaf(a2, f.x, acc.z); acc.w = fmaf(a2, f.y, acc.w);
        f = __half22float2(*(__half2*)&u3.x); acc.x = fmaf(a3, f.x, acc.x); acc.y = fmaf(a3, f.y, acc.y);
        f = __half22float2(*(__half2*)&u3.y); acc.z = fmaf(a3, f.x, acc.z); acc.w = fmaf(a3, f.y, acc.w);
    }
    for (; i < end; i++) {
        int s = g_csr_src[i];
        float a = __expf(lrelu(g_el1[s * 4 + hsel] + erh));
        uint2 u = *(const uint2*)&g_feat1h[s * 256 + coff];
        float2 f0 = __half22float2(*(__half2*)&u.x);
        float2 f1 = __half22float2(*(__half2*)&u.y);
        dn += a;
        acc.x = fmaf(a, f0.x, acc.x); acc.y = fmaf(a, f0.y, acc.y);
        acc.z = fmaf(a, f1.x, acc.z); acc.w = fmaf(a, f1.y, acc.w);
    }
    float inv = 1.f / fmaxf(dn, 1e-9f);
    acc.x *= inv; acc.y *= inv; acc.z *= inv; acc.w *= inv;
    acc.x = acc.x > 0.f ? acc.x : __expf(acc.x) - 1.f;
    acc.y = acc.y > 0.f ? acc.y : __expf(acc.y) - 1.f;
    acc.z = acc.z > 0.f ? acc.z : __expf(acc.z) - 1.f;
    acc.w = acc.w > 0.f ? acc.w : __expf(acc.w) - 1.f;
    *(float4*)&g_h[node * 256 + coff] = acc;
}

// ---------------- GEMM2: feat2 = h @ W2  ([NN,256] x [256,47->64pad]), fused el2/er2 ----
// 64x64 tile, 4x4 microtile, f32x2 FMA, W2 staged per k-chunk (cols 47..63 zero).
__global__ __launch_bounds__(256) void gemm2_kernel(const float* __restrict__ W2,
                                                    const float* __restrict__ al2,
                                                    const float* __restrict__ ar2) {
    __shared__ float As[16][64];
    __shared__ float Bs[16][64];
    int tid = threadIdx.x;             // 256 threads
    int tx = tid & 15, ty = tid >> 4;
    int rowBase = blockIdx.x * 64;
    int c0 = tx * 4;

    float alv[4], arv[4];
#pragma unroll
    for (int j = 0; j < 4; j++) {
        int c = c0 + j;
        alv[j] = (c < 47) ? al2[c] : 0.f;
        arv[j] = (c < 47) ? ar2[c] : 0.f;
    }

    int aR = tid >> 2, aK = (tid & 3) * 4;      // A: 64 rows x 16 k
    int bK = tid >> 4, bC = (tid & 15) * 4;     // B: 16 k x 64 cols

    unsigned long long acc[4][2];
#pragma unroll
    for (int i = 0; i < 4; i++) { acc[i][0] = 0ull; acc[i][1] = 0ull; }

    for (int k0 = 0; k0 < 256; k0 += 16) {
        int row = rowBase + aR;
        float4 va = (row < NN) ? *(const float4*)&g_h[row * 256 + k0 + aK]
                               : make_float4(0.f, 0.f, 0.f, 0.f);
        As[aK + 0][aR] = va.x; As[aK + 1][aR] = va.y;
        As[aK + 2][aR] = va.z; As[aK + 3][aR] = va.w;
#pragma unroll
        for (int j = 0; j < 4; j++) {
            int c = bC + j;
            Bs[bK][c] = (c < 47) ? W2[(k0 + bK) * 47 + c] : 0.f;
        }
        __syncthreads();
#pragma unroll
        for (int k = 0; k < 16; k++) {
            float4 a4 = *(const float4*)&As[k][ty * 4];
            ulonglong2 bq = *(const ulonglong2*)&Bs[k][tx * 4];
            float av[4] = {a4.x, a4.y, a4.z, a4.w};
#pragma unroll
            for (int i = 0; i < 4; i++) {
                unsigned long long ad;
                asm("mov.b64 %0, {%1, %1};" : "=l"(ad) : "f"(av[i]));
                asm("fma.rn.f32x2 %0, %1, %2, %0;" : "+l"(acc[i][0]) : "l"(ad), "l"(bq.x));
                asm("fma.rn.f32x2 %0, %1, %2, %0;" : "+l"(acc[i][1]) : "l"(ad), "l"(bq.y));
            }
        }
        __syncthreads();
    }

#pragma unroll
    for (int i = 0; i < 4; i++) {
        int row = rowBase + ty * 4 + i;
        float c[4];
        asm("mov.b64 {%0, %1}, %2;" : "=f"(c[0]), "=f"(c[1]) : "l"(acc[i][0]));
        asm("mov.b64 {%0, %1}, %2;" : "=f"(c[2]), "=f"(c[3]) : "l"(acc[i][1]));
        float el = 0.f, er = 0.f;
#pragma unroll
        for (int j = 0; j < 4; j++) {
            el = fmaf(c[j], alv[j], el);
            er = fmaf(c[j], arv[j], er);
        }
        // reduce across 16 col-threads (contiguous 16-lane halves of the warp)
#pragma unroll
        for (int off = 8; off; off >>= 1) {
            el += __shfl_xor_sync(0xffffffffu, el, off);
            er += __shfl_xor_sync(0xffffffffu, er, off);
        }
        if (row < NN) {
            if (tx < 12) {
                float4 st = make_float4(c[0], c[1], c[2], (c0 + 3 < 47) ? c[3] : 0.f);
                *(float4*)&g_feat2[row * 48 + c0] = st;
            }
            if (tx == 0) { g_el2[row] = el; g_er2[row] = er; }
        }
    }
}

// ---------------- layer-2 gather + fused log-softmax (warp per node, single pass) ------
__global__ void gather2_kernel(float* __restrict__ out) {
    int gw = (blockIdx.x * blockDim.x + threadIdx.x) >> 5;
    int lane = threadIdx.x & 31;
    if (gw >= NN) return;
    int node = gw;
    int beg = g_rowstart[node], end = g_rowstart[node + 1];
    float erv = g_er2[node];
    int j1 = lane + 32;
    bool hasJ1 = (j1 < 47);
    int j1c = hasJ1 ? j1 : 47;                 // col 47 is zero-padded

    float acc0 = 0.f, acc1 = 0.f, dn = 0.f;
    int i = beg;
    for (; i + 4 <= end; i += 4) {
        int s0 = g_csr_src[i],     s1 = g_csr_src[i + 1];
        int s2 = g_csr_src[i + 2], s3 = g_csr_src[i + 3];
        float e0 = g_el2[s0], e1 = g_el2[s1], e2 = g_el2[s2], e3 = g_el2[s3];
        float f00 = g_feat2[s0 * 48 + lane], f01 = g_feat2[s0 * 48 + j1c];
        float f10 = g_feat2[s1 * 48 + lane], f11 = g_feat2[s1 * 48 + j1c];
        float f20 = g_feat2[s2 * 48 + lane], f21 = g_feat2[s2 * 48 + j1c];
        float f30 = g_feat2[s3 * 48 + lane], f31 = g_feat2[s3 * 48 + j1c];
        float a0 = __expf(lrelu(e0 + erv));
        float a1 = __expf(lrelu(e1 + erv));
        float a2 = __expf(lrelu(e2 + erv));
        float a3 = __expf(lrelu(e3 + erv));
        dn += (a0 + a1) + (a2 + a3);
        acc0 = fmaf(a0, f00, acc0); acc1 = fmaf(a0, f01, acc1);
        acc0 = fmaf(a1, f10, acc0); acc1 = fmaf(a1, f11, acc1);
        acc0 = fmaf(a2, f20, acc0); acc1 = fmaf(a2, f21, acc1);
        acc0 = fmaf(a3, f30, acc0); acc1 = fmaf(a3, f31, acc1);
    }
    for (; i < end; i++) {
        int s = g_csr_src[i];
        float a = __expf(lrelu(g_el2[s] + erv));
        dn += a;
        acc0 = fmaf(a, g_feat2[s * 48 + lane], acc0);
        acc1 = fmaf(a, g_feat2[s * 48 + j1c], acc1);
    }
    float inv = 1.f / fmaxf(dn, 1e-9f);
    acc0 *= inv; acc1 *= inv;

    // log_softmax over 47 logits
    float m2 = fmaxf(acc0, hasJ1 ? acc1 : -CUDART_INF_F);
#pragma unroll
    for (int off = 16; off; off >>= 1)
        m2 = fmaxf(m2, __shfl_xor_sync(0xffffffffu, m2, off));
    float se = __expf(acc0 - m2) + (hasJ1 ? __expf(acc1 - m2) : 0.f);
#pragma unroll
    for (int off = 16; off; off >>= 1)
        se += __shfl_xor_sync(0xffffffffu, se, off);
    float ls = logf(se);
    out[node * 47 + lane] = acc0 - m2 - ls;
    if (hasJ1) out[node * 47 + j1] = acc1 - m2 - ls;
}

// ---------------- launch ----------------
extern "C" void kernel_launch(void* const* d_in, const int* in_sizes, int n_in,
                              void* d_out, int out_size) {
    const float* features = (const float*)d_in[0];
    const int*   src      = (const int*)  d_in[1];
    const int*   dst      = (const int*)  d_in[2];
    const float* W1       = (const float*)d_in[3];
    const float* al1      = (const float*)d_in[4];
    const float* ar1      = (const float*)d_in[5];
    const float* W2       = (const float*)d_in[6];
    const float* al2      = (const float*)d_in[7];
    const float* ar2      = (const float*)d_in[8];
    float* out = (float*)d_out;

    // Fork the CSR build onto a side stream so it overlaps GEMM1.
    cudaStream_t s2;
    cudaEvent_t evFork, evJoin;
    cudaStreamCreateWithFlags(&s2, cudaStreamNonBlocking);
    cudaEventCreateWithFlags(&evFork, cudaEventDisableTiming);
    cudaEventCreateWithFlags(&evJoin, cudaEventDisableTiming);

    cudaEventRecord(evFork, 0);
    cudaStreamWaitEvent(s2, evFork, 0);
    init_kernel<<<(NN + 255) / 256, 256, 0, s2>>>();
    count_kernel<<<(NE + 255) / 256, 256, 0, s2>>>(dst);
    scan_kernel<<<1, 1024, 0, s2>>>();
    scatter_kernel<<<(NE + 255) / 256, 256, 0, s2>>>(src, dst);
    cudaEventRecord(evJoin, s2);

    dim3 g1(2, (NN + 127) / 128);
    gemm1_kernel<<<g1, 256>>>(features, W1, al1, ar1);

    cudaStreamWaitEvent(0, evJoin, 0);
    gather1_kernel<<<(2 * NN + 7) / 8, 256>>>();
    gemm2_kernel<<<(NN + 63) / 64, 256>>>(W2, al2, ar2);
    gather2_kernel<<<(NN + 7) / 8, 256>>>(out);
}